// round 9
// baseline (speedup 1.0000x reference)
#include <cuda_runtime.h>
#include <cuda_bf16.h>

// ProjectBEV: input (B=16, H=64, W=2048, CK=3, 2) float32.
// Flattened element order (B, CK, H, W); N = 6,291,456.
// Output (float32, concatenated):
//   [0   , 6N )  presence_indices rows [b, qx, qy, c, h, w]
//   [6N  , 7N )  presence_vals (all 1)
//   [7N  , 21N)  position_indices rows [b, qx, qy, c, h, w, d], d=0,1
//   [21N , 23N)  position_vals [sx, sy]
// sx = 2x+1, sy = 2y+81, qx = trunc(sx), qy = trunc(sy).
//
// R9: SMEM-staged spans. One 768-thread block owns (b, h, 256 w) x all 3
// channels. 384 threads read the input span as linear float4 (each byte
// fetched once -> minimal L1 wavefronts), de-interleave into padded
// per-channel SMEM; then 384 threads write position_indices units and 384
// write presence_indices + position_vals (+presence_vals fill). All store
// warps are channel-uniform -> perfect STG.128 coalescing.

#define NSPAN_W 256                      // w elements per span
#define CH_STRIDE 258                    // float2 stride per channel (pad 2)

__global__ __launch_bounds__(768)
void project_bev_kernel(const float4* __restrict__ in,
                        float* __restrict__ out,
                        long N)
{
    __shared__ __align__(16) float sm[3 * CH_STRIDE * 2];  // 6192 B

    const int s   = blockIdx.x;          // 16*64*8 = 8192 spans
    const int b   = s >> 9;
    const int h   = (s >> 3) & 63;
    const int wc  = s & 7;               // w chunk: w_base = wc*256
    const int tid = threadIdx.x;

    // ---- stage: 384 linear float4 loads, de-interleave by channel ----
    if (tid < 384) {
        const long f4_base =
            ((long)((b * 64 + h) * 2048 + (wc << 8)) * 6) >> 2;
        const float4 v = __ldcs(in + f4_base + tid);

        const int j0 = 2 * tid;          // local (x,y)-pair index
        const int c0 = j0 % 3, w0 = j0 / 3;
        const int j1 = j0 + 1;
        const int c1 = j1 % 3, w1 = j1 / 3;
        float2* sm2 = (float2*)sm;
        sm2[c0 * CH_STRIDE + w0] = make_float2(v.x, v.y);
        sm2[c1 * CH_STRIDE + w1] = make_float2(v.z, v.w);
    }
    __syncthreads();

    // ---- unit decode: A = position_indices, B = presence + vals ----
    const bool isA = tid < 384;
    const int  u   = isA ? tid : tid - 384;   // 0..383
    const int  c   = u >> 7;                  // warp-uniform (128 = 4 warps)
    const int  p   = u & 127;                 // w-pair within span

    // conflict-free LDS.128: (c*258 + 2p) is even -> 16B aligned
    const float4 xy = *(const float4*)(sm + (c * CH_STRIDE + 2 * p) * 2);

    const float sx0 = xy.x * 2.0f + 1.0f;
    const float sy0 = xy.y * 2.0f + 81.0f;
    const float sx1 = xy.z * 2.0f + 1.0f;
    const float sy1 = xy.w * 2.0f + 81.0f;
    const float qx0 = (float)(int)sx0;   // positive -> trunc == astype(int64)
    const float qy0 = (float)(int)sy0;
    const float qx1 = (float)(int)sx1;
    const float qy1 = (float)(int)sy1;

    const float bf  = (float)b;
    const float cf  = (float)c;
    const float hf  = (float)h;
    const float wf0 = (float)((wc << 8) + 2 * p);
    const float wf1 = wf0 + 1.0f;

    // global (x,y)-pair index in output element order
    const long t_g = ((long)((b * 3 + c) * 64 + h) << 10) + (wc << 7) + p;

    if (isA) {
        // ---- position_indices: 7 STG.128 at out[7N + 28*t_g] ----
        float4* q = (float4*)(out + 7 * N + 28 * t_g);
        __stcs(q + 0, make_float4(bf,   qx0, qy0,  cf ));
        __stcs(q + 1, make_float4(hf,   wf0, 0.0f, bf ));
        __stcs(q + 2, make_float4(qx0,  qy0, cf,   hf ));
        __stcs(q + 3, make_float4(wf0, 1.0f, bf,   qx1));
        __stcs(q + 4, make_float4(qy1,  cf,  hf,   wf1));
        __stcs(q + 5, make_float4(0.0f, bf,  qx1,  qy1));
        __stcs(q + 6, make_float4(cf,   hf,  wf1, 1.0f));
    } else {
        // ---- presence_indices: 3 STG.128 at out[12*t_g] ----
        float4* q = (float4*)(out + 12 * t_g);
        __stcs(q + 0, make_float4(bf,  qx0, qy0, cf ));
        __stcs(q + 1, make_float4(hf,  wf0, bf,  qx1));
        __stcs(q + 2, make_float4(qy1, cf,  hf,  wf1));

        // ---- position_vals: 1 STG.128 at out[21N + 4*t_g] ----
        __stcs((float4*)(out + 21 * N + 4 * t_g),
               make_float4(sx0, sy0, sx1, sy1));

        // ---- presence_vals: 192 threads fill 768 floats for the span ----
        if (u < 192) {
            const int cc  = u >> 6;            // warp-uniform (64 = 2 warps)
            const int f4i = u & 63;
            float* base = out + 6 * N
                        + ((long)((b * 3 + cc) * 64 + h) << 11)
                        + (wc << 8) + 4 * f4i;
            __stcs((float4*)base, make_float4(1.0f, 1.0f, 1.0f, 1.0f));
        }
    }
}

extern "C" void kernel_launch(void* const* d_in, const int* in_sizes, int n_in,
                              void* d_out, int out_size)
{
    const float4* in = (const float4*)d_in[0];
    float* out = (float*)d_out;

    const long N = (long)in_sizes[0] / 2;    // number of (x,y) points
    const int blocks = (int)(N / (3 * NSPAN_W));   // 8192 spans

    project_bev_kernel<<<blocks, 768>>>(in, out, N);
}

// round 10
// speedup vs baseline: 1.8509x; 1.8509x over previous
#include <cuda_runtime.h>
#include <cuda_bf16.h>

// ProjectBEV: input (B=16, H=64, W=2048, CK=3, 2) float32.
// Flattened element order (B, CK, H, W); N = 6,291,456.
// Output (float32, concatenated):
//   [0   , 6N )  presence_indices rows [b, qx, qy, c, h, w]
//   [6N  , 7N )  presence_vals (all 1)
//   [7N  , 21N)  position_indices rows [b, qx, qy, c, h, w, d], d=0,1
//   [21N , 23N)  position_vals [sx, sy]
// sx = 2x+1, sy = 2y+81, qx = trunc(sx), qy = trunc(sy).
//
// R10: warp-cooperative coalesced stores. Lane l owns pair (span*256+tid);
// output float4 slot j = 32m + lane is filled by shuffling pair j/7 (or j/3)
// q-values from its owner lane and selecting word j%7 (j%3) components.
// Every STG.128 is lane-contiguous -> minimal store wavefronts (was 7x/3x
// inflated at 112B/48B lane strides in R8).

__global__ __launch_bounds__(256)
void project_bev_kernel(const float* __restrict__ in,
                        float* __restrict__ out,
                        long N)
{
    const int  role = (int)(blockIdx.x % 3);   // 0=presence, 1=position, 2=vals
    const long span = (long)(blockIdx.x / 3);  // 256 pairs per span
    const int  tid  = threadIdx.x;
    const int  lane = tid & 31;

    // ---- this thread's pair ----
    const long P  = span * 256 + tid;
    const long i0 = P << 1;
    const int w0 = (int)(i0 & 2047);
    const int h  = (int)((i0 >> 11) & 63);
    const int hi = (int)(i0 >> 17);            // b*3 + c
    const int b  = hi / 3;
    const int c  = hi - 3 * b;

    // input offset in float2 units: (((b*64+h)*2048 + w0)*3 + c)
    const long in_off = ((long)((b * 64 + h) * 2048 + w0)) * 3 + c;
    const float2 e0 = __ldg(((const float2*)in) + in_off);
    const float2 e1 = __ldg(((const float2*)in) + in_off + 3);

    const float sx0 = e0.x * 2.0f + 1.0f;
    const float sy0 = e0.y * 2.0f + 81.0f;
    const float sx1 = e1.x * 2.0f + 1.0f;
    const float sy1 = e1.y * 2.0f + 81.0f;

    if (role == 2) {
        // position_vals: lane-contiguous float4 per pair
        __stcs((float4*)(out + 21 * N + 4 * P), make_float4(sx0, sy0, sx1, sy1));
        // presence_vals: 512 floats per span
        if (tid < 128)
            __stcs((float4*)(out + 6 * N + span * 512) + tid,
                   make_float4(1.0f, 1.0f, 1.0f, 1.0f));
        return;
    }

    const float qx0 = (float)(int)sx0;   // positive -> trunc == astype(int64)
    const float qy0 = (float)(int)sy0;
    const float qx1 = (float)(int)sx1;
    const float qy1 = (float)(int)sy1;
    const float bf = (float)b;           // warp-uniform
    const float cf = (float)c;           // warp-uniform
    const float hf = (float)h;           // warp-uniform

    const long  pairbase = span * 256 + (long)(tid & ~31);   // warp's first pair
    const float wbase = (float)(int)((pairbase << 1) & 2047); // warp-uniform

    if (role == 1) {
        // ---- position_indices: 7 float4 per pair, warp-cooperative ----
        float4* base4 = (float4*)(out + 7 * N) + 7 * pairbase;
#pragma unroll
        for (int m = 0; m < 7; m++) {
            const int j = 32 * m + lane;
            const int p = j / 7;
            const int k = j - 7 * p;
            const float X0 = __shfl_sync(0xffffffffu, qx0, p);
            const float Y0 = __shfl_sync(0xffffffffu, qy0, p);
            const float X1 = __shfl_sync(0xffffffffu, qx1, p);
            const float Y1 = __shfl_sync(0xffffffffu, qy1, p);
            const float W0 = wbase + 2.0f * (float)p;
            const float W1 = W0 + 1.0f;
            // word k of [b,qx0,qy0,c | h,w0,0,b | qx0,qy0,c,h | w0,1,b,qx1 |
            //            qy1,c,h,w1 | 0,b,qx1,qy1 | c,h,w1,1]
            const float c0 = k==0?bf : k==1?hf  : k==2?X0 : k==3?W0   : k==4?Y1 : k==5?0.0f : cf;
            const float c1 = k==0?X0 : k==1?W0  : k==2?Y0 : k==3?1.0f : k==4?cf : k==5?bf   : hf;
            const float c2 = k==0?Y0 : k==1?0.0f: k==2?cf : k==3?bf   : k==4?hf : k==5?X1   : W1;
            const float c3 = k==0?cf : k==1?bf  : k==2?hf : k==3?X1   : k==4?W1 : k==5?Y1   : 1.0f;
            __stcs(base4 + j, make_float4(c0, c1, c2, c3));
        }
    } else {
        // ---- presence_indices: 3 float4 per pair, warp-cooperative ----
        float4* base4 = (float4*)out + 3 * pairbase;
#pragma unroll
        for (int m = 0; m < 3; m++) {
            const int j = 32 * m + lane;
            const int p = j / 3;
            const int k = j - 3 * p;
            const float X0 = __shfl_sync(0xffffffffu, qx0, p);
            const float Y0 = __shfl_sync(0xffffffffu, qy0, p);
            const float X1 = __shfl_sync(0xffffffffu, qx1, p);
            const float Y1 = __shfl_sync(0xffffffffu, qy1, p);
            const float W0 = wbase + 2.0f * (float)p;
            const float W1 = W0 + 1.0f;
            // word k of [b,qx0,qy0,c | h,w0,b,qx1 | qy1,c,h,w1]
            const float c0 = k==0?bf : k==1?hf : Y1;
            const float c1 = k==0?X0 : k==1?W0 : cf;
            const float c2 = k==0?Y0 : k==1?bf : hf;
            const float c3 = k==0?cf : k==1?X1 : W1;
            __stcs(base4 + j, make_float4(c0, c1, c2, c3));
        }
    }
}

extern "C" void kernel_launch(void* const* d_in, const int* in_sizes, int n_in,
                              void* d_out, int out_size)
{
    const float* in = (const float*)d_in[0];
    float* out = (float*)d_out;

    const long N = (long)in_sizes[0] / 2;        // number of (x,y) points
    const long spans = N / 512;                  // 256 pairs per span (exact)
    const int  blocks = (int)(spans * 3);        // 3 roles per span

    project_bev_kernel<<<blocks, 256>>>(in, out, N);
}